// round 2
// baseline (speedup 1.0000x reference)
#include <cuda_runtime.h>
#include <math.h>

#define TT      2048
#define HIDDEN  5120
#define NH      32
#define NHG     8        // heads per attention group (4 groups)
#define DQ      128
#define DR      64
#define DV      128
#define QLORA   1536
#define KVLORA  512

// ---------------- scratch (device globals: allocation-free) ----------------
__device__ float g_qa[(size_t)TT * QLORA];                 // 12 MB
__device__ float g_q[(size_t)TT * NH * (DQ + DR)];         // 48 MB
__device__ float g_kv[(size_t)TT * (KVLORA + DR)];         // 4.5 MB
__device__ float g_kvup[(size_t)TT * NH * (DQ + DV)];      // 64 MB
__device__ float g_kfull[(size_t)TT * NH * (DQ + DR)];     // 48 MB
__device__ float g_scores[(size_t)NHG * TT * TT];          // 128 MB (reused x4)
__device__ float g_attnout[(size_t)TT * NH * DV];          // 32 MB

// ---------------- reductions ----------------
__device__ __forceinline__ float blockReduceSum(float v) {
    __shared__ float sh[32];
    __syncthreads();
    #pragma unroll
    for (int o = 16; o > 0; o >>= 1) v += __shfl_down_sync(0xffffffffu, v, o);
    int w = threadIdx.x >> 5;
    if ((threadIdx.x & 31) == 0) sh[w] = v;
    __syncthreads();
    if (w == 0) {
        v = (threadIdx.x < (blockDim.x >> 5)) ? sh[threadIdx.x] : 0.0f;
        #pragma unroll
        for (int o = 16; o > 0; o >>= 1) v += __shfl_down_sync(0xffffffffu, v, o);
        if (threadIdx.x == 0) sh[0] = v;
    }
    __syncthreads();
    return sh[0];
}

__device__ __forceinline__ float blockReduceMax(float v) {
    __shared__ float sh[32];
    __syncthreads();
    #pragma unroll
    for (int o = 16; o > 0; o >>= 1) v = fmaxf(v, __shfl_down_sync(0xffffffffu, v, o));
    int w = threadIdx.x >> 5;
    if ((threadIdx.x & 31) == 0) sh[w] = v;
    __syncthreads();
    if (w == 0) {
        v = (threadIdx.x < (blockDim.x >> 5)) ? sh[threadIdx.x] : -3.4e38f;
        #pragma unroll
        for (int o = 16; o > 0; o >>= 1) v = fmaxf(v, __shfl_down_sync(0xffffffffu, v, o));
        if (threadIdx.x == 0) sh[0] = v;
    }
    __syncthreads();
    return sh[0];
}

// ---------------- SGEMM NN: C = A(MxK) * B(KxN), row-major, batched ----------------
// 128x128 block tile, BK=8, 256 threads, 8x8 per thread.
// CAUSAL_K: truncate K-loop at rowBase+128 (P columns above that are exact zeros).
template<bool CAUSAL_K>
__global__ void __launch_bounds__(256) sgemm_nn(
    int M, int N, int K,
    const float* __restrict__ A, int lda, long long strideA,
    const float* __restrict__ B, int ldb, long long strideB,
    float* __restrict__ C, int ldc, long long strideC)
{
    const int bx = blockIdx.x, by = blockIdx.y, bz = blockIdx.z;
    A += (long long)bz * strideA;
    B += (long long)bz * strideB;
    C += (long long)bz * strideC;

    __shared__ float As[8][128];
    __shared__ float Bs[8][128];

    const int tid = threadIdx.x;
    const int ty = tid >> 4, tx = tid & 15;
    const int rowBase = by * 128, colBase = bx * 128;

    const int aRow = tid >> 1, aCol = (tid & 1) * 4;   // A tile: 128 rows x 8 k
    const int bRow = tid >> 5, bCol = (tid & 31) * 4;  // B tile: 8 k x 128 cols

    float acc[8][8];
    #pragma unroll
    for (int i = 0; i < 8; i++)
        #pragma unroll
        for (int j = 0; j < 8; j++) acc[i][j] = 0.0f;

    int kEnd = K;
    if (CAUSAL_K) kEnd = min(K, rowBase + 128);

    for (int k0 = 0; k0 < kEnd; k0 += 8) {
        {
            int gr = rowBase + aRow;
            float4 v = make_float4(0.f, 0.f, 0.f, 0.f);
            if (gr < M)
                v = *reinterpret_cast<const float4*>(&A[(long long)gr * lda + k0 + aCol]);
            As[aCol + 0][aRow] = v.x;
            As[aCol + 1][aRow] = v.y;
            As[aCol + 2][aRow] = v.z;
            As[aCol + 3][aRow] = v.w;
        }
        {
            int gc = colBase + bCol;
            float4 v = make_float4(0.f, 0.f, 0.f, 0.f);
            if (gc < N)
                v = *reinterpret_cast<const float4*>(&B[(long long)(k0 + bRow) * ldb + gc]);
            *reinterpret_cast<float4*>(&Bs[bRow][bCol]) = v;
        }
        __syncthreads();

        #pragma unroll
        for (int kk = 0; kk < 8; kk++) {
            float4 a0 = *reinterpret_cast<const float4*>(&As[kk][ty * 8]);
            float4 a1 = *reinterpret_cast<const float4*>(&As[kk][ty * 8 + 4]);
            float4 b0 = *reinterpret_cast<const float4*>(&Bs[kk][tx * 8]);
            float4 b1 = *reinterpret_cast<const float4*>(&Bs[kk][tx * 8 + 4]);
            float ra[8] = {a0.x, a0.y, a0.z, a0.w, a1.x, a1.y, a1.z, a1.w};
            float rb[8] = {b0.x, b0.y, b0.z, b0.w, b1.x, b1.y, b1.z, b1.w};
            #pragma unroll
            for (int i = 0; i < 8; i++)
                #pragma unroll
                for (int j = 0; j < 8; j++)
                    acc[i][j] += ra[i] * rb[j];
        }
        __syncthreads();
    }

    #pragma unroll
    for (int i = 0; i < 8; i++) {
        int gr = rowBase + ty * 8 + i;
        if (gr >= M) continue;
        #pragma unroll
        for (int j = 0; j < 8; j += 4) {
            int gc = colBase + tx * 8 + j;
            if (gc < N) {
                float4 v = make_float4(acc[i][j], acc[i][j + 1], acc[i][j + 2], acc[i][j + 3]);
                *reinterpret_cast<float4*>(&C[(long long)gr * ldc + gc]) = v;
            }
        }
    }
}

// ---------------- SGEMM NT: C = A(MxK) * B(NxK)^T, row-major, batched ----------------
// CAUSAL_SKIP: skip blocks fully above the diagonal (never read by softmax).
template<bool CAUSAL_SKIP>
__global__ void __launch_bounds__(256) sgemm_nt(
    int M, int N, int K,
    const float* __restrict__ A, int lda, long long strideA,
    const float* __restrict__ B, int ldb, long long strideB,
    float* __restrict__ C, int ldc, long long strideC)
{
    const int bx = blockIdx.x, by = blockIdx.y, bz = blockIdx.z;
    if (CAUSAL_SKIP && bx > by) return;  // block cols entirely above row diagonal
    A += (long long)bz * strideA;
    B += (long long)bz * strideB;
    C += (long long)bz * strideC;

    __shared__ float As[8][128];
    __shared__ float Bs[8][128];

    const int tid = threadIdx.x;
    const int ty = tid >> 4, tx = tid & 15;
    const int rowBase = by * 128, colBase = bx * 128;

    const int aRow = tid >> 1, aCol = (tid & 1) * 4;

    float acc[8][8];
    #pragma unroll
    for (int i = 0; i < 8; i++)
        #pragma unroll
        for (int j = 0; j < 8; j++) acc[i][j] = 0.0f;

    for (int k0 = 0; k0 < K; k0 += 8) {
        {
            int gr = rowBase + aRow;
            float4 v = make_float4(0.f, 0.f, 0.f, 0.f);
            if (gr < M)
                v = *reinterpret_cast<const float4*>(&A[(long long)gr * lda + k0 + aCol]);
            As[aCol + 0][aRow] = v.x;
            As[aCol + 1][aRow] = v.y;
            As[aCol + 2][aRow] = v.z;
            As[aCol + 3][aRow] = v.w;
        }
        {
            int gn = colBase + aRow;
            float4 v = make_float4(0.f, 0.f, 0.f, 0.f);
            if (gn < N)
                v = *reinterpret_cast<const float4*>(&B[(long long)gn * ldb + k0 + aCol]);
            Bs[aCol + 0][aRow] = v.x;
            Bs[aCol + 1][aRow] = v.y;
            Bs[aCol + 2][aRow] = v.z;
            Bs[aCol + 3][aRow] = v.w;
        }
        __syncthreads();

        #pragma unroll
        for (int kk = 0; kk < 8; kk++) {
            float4 a0 = *reinterpret_cast<const float4*>(&As[kk][ty * 8]);
            float4 a1 = *reinterpret_cast<const float4*>(&As[kk][ty * 8 + 4]);
            float4 b0 = *reinterpret_cast<const float4*>(&Bs[kk][tx * 8]);
            float4 b1 = *reinterpret_cast<const float4*>(&Bs[kk][tx * 8 + 4]);
            float ra[8] = {a0.x, a0.y, a0.z, a0.w, a1.x, a1.y, a1.z, a1.w};
            float rb[8] = {b0.x, b0.y, b0.z, b0.w, b1.x, b1.y, b1.z, b1.w};
            #pragma unroll
            for (int i = 0; i < 8; i++)
                #pragma unroll
                for (int j = 0; j < 8; j++)
                    acc[i][j] += ra[i] * rb[j];
        }
        __syncthreads();
    }

    #pragma unroll
    for (int i = 0; i < 8; i++) {
        int gr = rowBase + ty * 8 + i;
        if (gr >= M) continue;
        #pragma unroll
        for (int j = 0; j < 8; j += 4) {
            int gc = colBase + tx * 8 + j;
            if (gc < N) {
                float4 v = make_float4(acc[i][j], acc[i][j + 1], acc[i][j + 2], acc[i][j + 3]);
                *reinterpret_cast<float4*>(&C[(long long)gr * ldc + gc]) = v;
            }
        }
    }
}

// ---------------- rmsnorm (in place over first n cols of each row) ----------------
__global__ void __launch_bounds__(256) rmsnorm_kernel(
    float* __restrict__ x, const float* __restrict__ g, int n, int ld)
{
    float* row = x + (size_t)blockIdx.x * ld;
    float ss = 0.0f;
    for (int k = threadIdx.x; k < n; k += 256) {
        float v = row[k];
        ss += v * v;
    }
    ss = blockReduceSum(ss);
    float r = rsqrtf(ss / (float)n + 1e-6f);
    for (int k = threadIdx.x; k < n; k += 256)
        row[k] = row[k] * r * g[k];
}

// ---------------- RoPE (GPT-J interleave, concat(freqs,freqs) angles) -------------
__global__ void __launch_bounds__(256) rope_kernel(
    float* __restrict__ q, float* __restrict__ kv, const int* __restrict__ positions)
{
    const int t = blockIdx.x;
    const float pos = (float)positions[t];
    __shared__ float cs[DR], sn[DR];
    if (threadIdx.x < DR) {
        int d = threadIdx.x;
        float invf = powf(10000.0f, -(float)(d & 31) / 32.0f);
        float a = pos * invf;
        cs[d] = cosf(a);
        sn[d] = sinf(a);
    }
    __syncthreads();

    // q_pe: 32 heads x 32 pairs
    for (int idx = threadIdx.x; idx < NH * 32; idx += 256) {
        int h = idx >> 5, i = idx & 31;
        float* p = q + (size_t)t * (NH * (DQ + DR)) + h * (DQ + DR) + DQ + 2 * i;
        float x0 = p[0], x1 = p[1];
        p[0] = x0 * cs[2 * i]     - x1 * sn[2 * i];
        p[1] = x1 * cs[2 * i + 1] + x0 * sn[2 * i + 1];
    }
    // k_pe: 32 pairs (shared across heads)
    if (threadIdx.x < 32) {
        int i = threadIdx.x;
        float* p = kv + (size_t)t * (KVLORA + DR) + KVLORA + 2 * i;
        float x0 = p[0], x1 = p[1];
        p[0] = x0 * cs[2 * i]     - x1 * sn[2 * i];
        p[1] = x1 * cs[2 * i + 1] + x0 * sn[2 * i + 1];
    }
}

// ---------------- assemble K_full = [k_nope | k_pe(bcast)] ----------------
__global__ void __launch_bounds__(256) assemble_kfull(
    const float* __restrict__ kvup, const float* __restrict__ kv, float* __restrict__ kfull)
{
    size_t idx = (size_t)blockIdx.x * 256 + threadIdx.x;
    const size_t total = (size_t)TT * NH * (DQ + DR);
    if (idx >= total) return;
    int d = (int)(idx % (DQ + DR));
    size_t th = idx / (DQ + DR);
    int h = (int)(th % NH);
    int t = (int)(th / NH);
    float v;
    if (d < DQ) v = kvup[(size_t)t * (NH * (DQ + DV)) + h * (DQ + DV) + d];
    else        v = kv[(size_t)t * (KVLORA + DR) + KVLORA + (d - DQ)];
    kfull[idx] = v;
}

// ---------------- causal softmax (in place; exact zeros above diagonal) -----------
__global__ void __launch_bounds__(256) softmax_kernel(float* __restrict__ scores)
{
    const int q = blockIdx.x;
    const int h = blockIdx.y;   // group-local head index
    float* row = scores + ((size_t)h * TT + (size_t)q) * TT;
    const int n = q + 1;
    const float scale = 0.07216878364870323f;  // (DQ+DR)^-0.5

    float m = -3.4e38f;
    for (int k = threadIdx.x; k < n; k += 256) m = fmaxf(m, row[k]);
    m = blockReduceMax(m);

    float s = 0.0f;
    for (int k = threadIdx.x; k < n; k += 256) {
        float e = __expf((row[k] - m) * scale);
        row[k] = e;
        s += e;
    }
    s = blockReduceSum(s);
    float inv = 1.0f / s;
    for (int k = threadIdx.x; k < n; k += 256) row[k] *= inv;
    for (int k = n + threadIdx.x; k < TT; k += 256) row[k] = 0.0f;
}

// ---------------- launcher ----------------
extern "C" void kernel_launch(void* const* d_in, const int* in_sizes, int n_in,
                              void* d_out, int out_size)
{
    const int*   positions = (const int*)  d_in[0];
    const float* hidden    = (const float*)d_in[1];
    const float* w_qa      = (const float*)d_in[2];
    const float* gamma_q   = (const float*)d_in[3];
    const float* w_qb      = (const float*)d_in[4];
    const float* w_kva     = (const float*)d_in[5];
    const float* gamma_kv  = (const float*)d_in[6];
    const float* w_kvb     = (const float*)d_in[7];
    const float* w_o       = (const float*)d_in[8];
    float* out = (float*)d_out;

    float *qa, *q, *kv, *kvup, *kfull, *scores, *attnout;
    cudaGetSymbolAddress((void**)&qa,      g_qa);
    cudaGetSymbolAddress((void**)&q,       g_q);
    cudaGetSymbolAddress((void**)&kv,      g_kv);
    cudaGetSymbolAddress((void**)&kvup,    g_kvup);
    cudaGetSymbolAddress((void**)&kfull,   g_kfull);
    cudaGetSymbolAddress((void**)&scores,  g_scores);
    cudaGetSymbolAddress((void**)&attnout, g_attnout);

    // 1) q_a = hidden @ w_qa            (2048x1536, K=5120)
    sgemm_nn<false><<<dim3(QLORA / 128, TT / 128, 1), 256>>>(
        TT, QLORA, HIDDEN, hidden, HIDDEN, 0, w_qa, QLORA, 0, qa, QLORA, 0);

    // 2) rmsnorm(q_a, gamma_q)
    rmsnorm_kernel<<<TT, 256>>>(qa, gamma_q, QLORA, QLORA);

    // 3) q = q_c @ w_qb                 (2048x6144, K=1536)
    sgemm_nn<false><<<dim3(NH * (DQ + DR) / 128, TT / 128, 1), 256>>>(
        TT, NH * (DQ + DR), QLORA, qa, QLORA, 0, w_qb, NH * (DQ + DR), 0,
        q, NH * (DQ + DR), 0);

    // 4) kv = hidden @ w_kva            (2048x576, K=5120)
    sgemm_nn<false><<<dim3((KVLORA + DR + 127) / 128, TT / 128, 1), 256>>>(
        TT, KVLORA + DR, HIDDEN, hidden, HIDDEN, 0, w_kva, KVLORA + DR, 0,
        kv, KVLORA + DR, 0);

    // 5) rmsnorm(kv_c, gamma_kv) — first 512 cols of each 576-stride row
    rmsnorm_kernel<<<TT, 256>>>(kv, gamma_kv, KVLORA, KVLORA + DR);

    // 6) kv_up = kv_c @ w_kvb           (2048x8192, K=512)
    sgemm_nn<false><<<dim3(NH * (DQ + DV) / 128, TT / 128, 1), 256>>>(
        TT, NH * (DQ + DV), KVLORA, kv, KVLORA + DR, 0, w_kvb, NH * (DQ + DV), 0,
        kvup, NH * (DQ + DV), 0);

    // 7) RoPE on q_pe (per head) and k_pe (in place)
    rope_kernel<<<TT, 256>>>(q, kv, positions);

    // 8) K_full assembly
    {
        size_t total = (size_t)TT * NH * (DQ + DR);
        assemble_kfull<<<(unsigned)((total + 255) / 256), 256>>>(kvup, kv, kfull);
    }

    // 9-11) attention, 4 groups of 8 heads (128 MB score scratch reused)
    for (int g = 0; g < NH / NHG; g++) {
        const int hOff = g * NHG;

        // scores[h] = Q_h @ K_h^T  (causal block-skip)
        sgemm_nt<true><<<dim3(TT / 128, TT / 128, NHG), 256>>>(
            TT, TT, DQ + DR,
            q     + (size_t)hOff * (DQ + DR), NH * (DQ + DR), (long long)(DQ + DR),
            kfull + (size_t)hOff * (DQ + DR), NH * (DQ + DR), (long long)(DQ + DR),
            scores, TT, (long long)TT * TT);

        // causal softmax in place
        softmax_kernel<<<dim3(TT, NHG), 256>>>(scores);

        // attn_out[h] = P_h @ V_h  (causal K truncation)
        sgemm_nn<true><<<dim3(DV / 128, TT / 128, NHG), 256>>>(
            TT, DV, TT,
            scores, TT, (long long)TT * TT,
            kvup + DQ + (size_t)hOff * (DQ + DV), NH * (DQ + DV), (long long)(DQ + DV),
            attnout + (size_t)hOff * DV, NH * DV, (long long)DV);
    }

    // 12) out = attn_out @ w_o          (2048x5120, K=4096)
    sgemm_nn<false><<<dim3(HIDDEN / 128, TT / 128, 1), 256>>>(
        TT, HIDDEN, NH * DV, attnout, NH * DV, 0, w_o, HIDDEN, 0, out, HIDDEN, 0);
}

// round 16
// speedup vs baseline: 2.7088x; 2.7088x over previous
#include <cuda_runtime.h>
#include <math.h>

#define TT      2048
#define HIDDEN  5120
#define NH      32
#define NHG     8        // heads per attention group (4 groups)
#define DQ      128
#define DR      64
#define DV      128
#define QLORA   1536
#define KVLORA  512
#define NCAT    (QLORA + KVLORA + DR)   // 2112

// ---------------- scratch (device globals: allocation-free) ----------------
__device__ float g_wcat[(size_t)HIDDEN * NCAT];            // 43 MB  [5120 x 2112]
__device__ float g_qakv[(size_t)TT * NCAT];                // 17 MB  [2048 x 2112]
__device__ float g_q[(size_t)TT * NH * (DQ + DR)];         // 48 MB
__device__ float g_kvup[(size_t)TT * NH * (DQ + DV)];      // 64 MB
__device__ float g_kfull[(size_t)TT * NH * (DQ + DR)];     // 48 MB
__device__ float g_scores[(size_t)NHG * TT * TT];          // 128 MB (reused x4)
__device__ float g_attnout[(size_t)TT * NH * DV];          // 32 MB

// ---------------- helpers ----------------
__device__ __forceinline__ unsigned f2tf(float f) {
    unsigned u;
    asm("cvt.rna.tf32.f32 %0, %1;" : "=r"(u) : "f"(f));
    return u;
}

__device__ __forceinline__ void mma_tf32(float c[4], const unsigned a[4], const unsigned b[2]) {
    asm volatile(
        "mma.sync.aligned.m16n8k8.row.col.f32.tf32.tf32.f32 "
        "{%0,%1,%2,%3}, {%4,%5,%6,%7}, {%8,%9}, {%0,%1,%2,%3};"
        : "+f"(c[0]), "+f"(c[1]), "+f"(c[2]), "+f"(c[3])
        : "r"(a[0]), "r"(a[1]), "r"(a[2]), "r"(a[3]), "r"(b[0]), "r"(b[1]));
}

__device__ __forceinline__ float blockReduceSum(float v) {
    __shared__ float sh[32];
    __syncthreads();
    #pragma unroll
    for (int o = 16; o > 0; o >>= 1) v += __shfl_down_sync(0xffffffffu, v, o);
    int w = threadIdx.x >> 5;
    if ((threadIdx.x & 31) == 0) sh[w] = v;
    __syncthreads();
    if (w == 0) {
        v = (threadIdx.x < (blockDim.x >> 5)) ? sh[threadIdx.x] : 0.0f;
        #pragma unroll
        for (int o = 16; o > 0; o >>= 1) v += __shfl_down_sync(0xffffffffu, v, o);
        if (threadIdx.x == 0) sh[0] = v;
    }
    __syncthreads();
    return sh[0];
}

__device__ __forceinline__ float blockReduceMax(float v) {
    __shared__ float sh[32];
    __syncthreads();
    #pragma unroll
    for (int o = 16; o > 0; o >>= 1) v = fmaxf(v, __shfl_down_sync(0xffffffffu, v, o));
    int w = threadIdx.x >> 5;
    if ((threadIdx.x & 31) == 0) sh[w] = v;
    __syncthreads();
    if (w == 0) {
        v = (threadIdx.x < (blockDim.x >> 5)) ? sh[threadIdx.x] : -3.4e38f;
        #pragma unroll
        for (int o = 16; o > 0; o >>= 1) v = fmaxf(v, __shfl_down_sync(0xffffffffu, v, o));
        if (threadIdx.x == 0) sh[0] = v;
    }
    __syncthreads();
    return sh[0];
}

// =================== tf32 MMA GEMM NN: C = A(MxK) @ B(KxN) =====================
// 128x128x16 CTA tile, 256 threads = 8 warps (2x4), warp tile 64x32,
// 16x m16n8k8 tf32 mma per warp per k-step. Row pad 8 => conflict-free frags.
// CAUSAL_K: truncate K-loop at rowBase+128 (upper part of P is exact zeros).
template<bool CAUSAL_K>
__global__ void __launch_bounds__(256) mma_nn(
    int M, int N, int K,
    const float* __restrict__ A, int lda, long long strideA,
    const float* __restrict__ B, int ldb, long long strideB,
    float* __restrict__ C, int ldc, long long strideC)
{
    const int bx = blockIdx.x, by = blockIdx.y, bz = blockIdx.z;
    A += (long long)bz * strideA;
    B += (long long)bz * strideB;
    C += (long long)bz * strideC;

    __shared__ unsigned As[16][136];
    __shared__ unsigned Bs[16][136];

    const int tid = threadIdx.x;
    const int lane = tid & 31, warp = tid >> 5;
    const int wr = warp >> 2, wc = warp & 3;
    const int g = lane >> 2, tg = lane & 3;
    const int rowBase = by * 128, colBase = bx * 128;

    const int aRow = tid >> 1, aK = (tid & 1) * 8;       // A: 128 rows x 16 k
    const int bK = tid >> 4,  bN = (tid & 15) * 8;       // B: 16 k x 128 n

    float acc[4][4][4];
    #pragma unroll
    for (int mi = 0; mi < 4; mi++)
        #pragma unroll
        for (int ni = 0; ni < 4; ni++)
            #pragma unroll
            for (int r = 0; r < 4; r++) acc[mi][ni][r] = 0.0f;

    int kEnd = K;
    if (CAUSAL_K) kEnd = min(K, rowBase + 128);

    for (int k0 = 0; k0 < kEnd; k0 += 16) {
        // stage A (transposed to k-major, tf32-converted)
        {
            const float* src = &A[(long long)(rowBase + aRow) * lda + k0 + aK];
            float4 v0 = *reinterpret_cast<const float4*>(src);
            float4 v1 = *reinterpret_cast<const float4*>(src + 4);
            As[aK + 0][aRow] = f2tf(v0.x);
            As[aK + 1][aRow] = f2tf(v0.y);
            As[aK + 2][aRow] = f2tf(v0.z);
            As[aK + 3][aRow] = f2tf(v0.w);
            As[aK + 4][aRow] = f2tf(v1.x);
            As[aK + 5][aRow] = f2tf(v1.y);
            As[aK + 6][aRow] = f2tf(v1.z);
            As[aK + 7][aRow] = f2tf(v1.w);
        }
        // stage B (k-major already, tf32-converted), N-edge guarded
        {
            int gc = colBase + bN;
            float4 v0 = make_float4(0.f, 0.f, 0.f, 0.f);
            float4 v1 = make_float4(0.f, 0.f, 0.f, 0.f);
            const float* src = &B[(long long)(k0 + bK) * ldb + gc];
            if (gc < N)     v0 = *reinterpret_cast<const float4*>(src);
            if (gc + 4 < N) v1 = *reinterpret_cast<const float4*>(src + 4);
            unsigned* dst = &Bs[bK][bN];
            dst[0] = f2tf(v0.x); dst[1] = f2tf(v0.y);
            dst[2] = f2tf(v0.z); dst[3] = f2tf(v0.w);
            dst[4] = f2tf(v1.x); dst[5] = f2tf(v1.y);
            dst[6] = f2tf(v1.z); dst[7] = f2tf(v1.w);
        }
        __syncthreads();

        #pragma unroll
        for (int ks = 0; ks < 2; ks++) {
            const int k8 = ks * 8;
            unsigned af[4][4], bf[4][2];
            #pragma unroll
            for (int mi = 0; mi < 4; mi++) {
                int m = wr * 64 + mi * 16 + g;
                af[mi][0] = As[k8 + tg][m];
                af[mi][1] = As[k8 + tg][m + 8];
                af[mi][2] = As[k8 + tg + 4][m];
                af[mi][3] = As[k8 + tg + 4][m + 8];
            }
            #pragma unroll
            for (int ni = 0; ni < 4; ni++) {
                int n = wc * 32 + ni * 8 + g;
                bf[ni][0] = Bs[k8 + tg][n];
                bf[ni][1] = Bs[k8 + tg + 4][n];
            }
            #pragma unroll
            for (int mi = 0; mi < 4; mi++)
                #pragma unroll
                for (int ni = 0; ni < 4; ni++)
                    mma_tf32(acc[mi][ni], af[mi], bf[ni]);
        }
        __syncthreads();
    }

    #pragma unroll
    for (int mi = 0; mi < 4; mi++) {
        int r0 = rowBase + wr * 64 + mi * 16 + g;
        #pragma unroll
        for (int ni = 0; ni < 4; ni++) {
            int c = colBase + wc * 32 + ni * 8 + 2 * tg;
            if (c < N) {
                float2 v01 = make_float2(acc[mi][ni][0], acc[mi][ni][1]);
                float2 v23 = make_float2(acc[mi][ni][2], acc[mi][ni][3]);
                *reinterpret_cast<float2*>(&C[(long long)r0 * ldc + c]) = v01;
                *reinterpret_cast<float2*>(&C[(long long)(r0 + 8) * ldc + c]) = v23;
            }
        }
    }
}

// =================== tf32 MMA GEMM NT: C = A(MxK) @ B(NxK)^T ===================
// CAUSAL_SKIP: skip blocks fully above the diagonal (never read by softmax).
template<bool CAUSAL_SKIP>
__global__ void __launch_bounds__(256) mma_nt(
    int M, int N, int K,
    const float* __restrict__ A, int lda, long long strideA,
    const float* __restrict__ B, int ldb, long long strideB,
    float* __restrict__ C, int ldc, long long strideC)
{
    const int bx = blockIdx.x, by = blockIdx.y, bz = blockIdx.z;
    if (CAUSAL_SKIP && bx > by) return;
    A += (long long)bz * strideA;
    B += (long long)bz * strideB;
    C += (long long)bz * strideC;

    __shared__ unsigned As[16][136];
    __shared__ unsigned Bs[16][136];

    const int tid = threadIdx.x;
    const int lane = tid & 31, warp = tid >> 5;
    const int wr = warp >> 2, wc = warp & 3;
    const int g = lane >> 2, tg = lane & 3;
    const int rowBase = by * 128, colBase = bx * 128;

    const int aRow = tid >> 1, aK = (tid & 1) * 8;

    float acc[4][4][4];
    #pragma unroll
    for (int mi = 0; mi < 4; mi++)
        #pragma unroll
        for (int ni = 0; ni < 4; ni++)
            #pragma unroll
            for (int r = 0; r < 4; r++) acc[mi][ni][r] = 0.0f;

    for (int k0 = 0; k0 < K; k0 += 16) {
        {
            const float* src = &A[(long long)(rowBase + aRow) * lda + k0 + aK];
            float4 v0 = *reinterpret_cast<const float4*>(src);
            float4 v1 = *reinterpret_cast<const float4*>(src + 4);
            As[aK + 0][aRow] = f2tf(v0.x);
            As[aK + 1][aRow] = f2tf(v0.y);
            As[aK + 2][aRow] = f2tf(v0.z);
            As[aK + 3][aRow] = f2tf(v0.w);
            As[aK + 4][aRow] = f2tf(v1.x);
            As[aK + 5][aRow] = f2tf(v1.y);
            As[aK + 6][aRow] = f2tf(v1.z);
            As[aK + 7][aRow] = f2tf(v1.w);
        }
        {
            const float* src = &B[(long long)(colBase + aRow) * ldb + k0 + aK];
            float4 v0 = *reinterpret_cast<const float4*>(src);
            float4 v1 = *reinterpret_cast<const float4*>(src + 4);
            Bs[aK + 0][aRow] = f2tf(v0.x);
            Bs[aK + 1][aRow] = f2tf(v0.y);
            Bs[aK + 2][aRow] = f2tf(v0.z);
            Bs[aK + 3][aRow] = f2tf(v0.w);
            Bs[aK + 4][aRow] = f2tf(v1.x);
            Bs[aK + 5][aRow] = f2tf(v1.y);
            Bs[aK + 6][aRow] = f2tf(v1.z);
            Bs[aK + 7][aRow] = f2tf(v1.w);
        }
        __syncthreads();

        #pragma unroll
        for (int ks = 0; ks < 2; ks++) {
            const int k8 = ks * 8;
            unsigned af[4][4], bf[4][2];
            #pragma unroll
            for (int mi = 0; mi < 4; mi++) {
                int m = wr * 64 + mi * 16 + g;
                af[mi][0] = As[k8 + tg][m];
                af[mi][1] = As[k8 + tg][m + 8];
                af[mi][2] = As[k8 + tg + 4][m];
                af[mi][3] = As[k8 + tg + 4][m + 8];
            }
            #pragma unroll
            for (int ni = 0; ni < 4; ni++) {
                int n = wc * 32 + ni * 8 + g;
                bf[ni][0] = Bs[k8 + tg][n];
                bf[ni][1] = Bs[k8 + tg + 4][n];
            }
            #pragma unroll
            for (int mi = 0; mi < 4; mi++)
                #pragma unroll
                for (int ni = 0; ni < 4; ni++)
                    mma_tf32(acc[mi][ni], af[mi], bf[ni]);
        }
        __syncthreads();
    }

    #pragma unroll
    for (int mi = 0; mi < 4; mi++) {
        int r0 = rowBase + wr * 64 + mi * 16 + g;
        #pragma unroll
        for (int ni = 0; ni < 4; ni++) {
            int c = colBase + wc * 32 + ni * 8 + 2 * tg;
            float2 v01 = make_float2(acc[mi][ni][0], acc[mi][ni][1]);
            float2 v23 = make_float2(acc[mi][ni][2], acc[mi][ni][3]);
            *reinterpret_cast<float2*>(&C[(long long)r0 * ldc + c]) = v01;
            *reinterpret_cast<float2*>(&C[(long long)(r0 + 8) * ldc + c]) = v23;
        }
    }
}

// ---------------- weight concat: wcat = [w_qa | w_kva] ----------------
__global__ void __launch_bounds__(256) concat_w(
    const float* __restrict__ wqa, const float* __restrict__ wkva, float* __restrict__ wcat)
{
    size_t idx = (size_t)blockIdx.x * 256 + threadIdx.x;
    const size_t total = (size_t)HIDDEN * NCAT;
    if (idx >= total) return;
    int col = (int)(idx % NCAT);
    int row = (int)(idx / NCAT);
    float v = (col < QLORA) ? wqa[(size_t)row * QLORA + col]
                            : wkva[(size_t)row * (KVLORA + DR) + (col - QLORA)];
    wcat[idx] = v;
}

// ---------------- rmsnorm (in place over first n cols of each row) ----------------
__global__ void __launch_bounds__(256) rmsnorm_kernel(
    float* __restrict__ x, const float* __restrict__ g, int n, int ld)
{
    float* row = x + (size_t)blockIdx.x * ld;
    float ss = 0.0f;
    for (int k = threadIdx.x; k < n; k += 256) {
        float v = row[k];
        ss += v * v;
    }
    ss = blockReduceSum(ss);
    float r = rsqrtf(ss / (float)n + 1e-6f);
    for (int k = threadIdx.x; k < n; k += 256)
        row[k] = row[k] * r * g[k];
}

// ---------------- RoPE (GPT-J interleave, concat(freqs,freqs) angles) -------------
__global__ void __launch_bounds__(256) rope_kernel(
    float* __restrict__ q, float* __restrict__ kpe, int kpeStride,
    const int* __restrict__ positions)
{
    const int t = blockIdx.x;
    const float pos = (float)positions[t];
    __shared__ float cs[DR], sn[DR];
    if (threadIdx.x < DR) {
        int d = threadIdx.x;
        float invf = powf(10000.0f, -(float)(d & 31) / 32.0f);
        float a = pos * invf;
        cs[d] = cosf(a);
        sn[d] = sinf(a);
    }
    __syncthreads();

    for (int idx = threadIdx.x; idx < NH * 32; idx += 256) {
        int h = idx >> 5, i = idx & 31;
        float* p = q + (size_t)t * (NH * (DQ + DR)) + h * (DQ + DR) + DQ + 2 * i;
        float x0 = p[0], x1 = p[1];
        p[0] = x0 * cs[2 * i]     - x1 * sn[2 * i];
        p[1] = x1 * cs[2 * i + 1] + x0 * sn[2 * i + 1];
    }
    if (threadIdx.x < 32) {
        int i = threadIdx.x;
        float* p = kpe + (size_t)t * kpeStride + 2 * i;
        float x0 = p[0], x1 = p[1];
        p[0] = x0 * cs[2 * i]     - x1 * sn[2 * i];
        p[1] = x1 * cs[2 * i + 1] + x0 * sn[2 * i + 1];
    }
}

// ---------------- assemble K_full = [k_nope | k_pe(bcast)] ----------------
__global__ void __launch_bounds__(256) assemble_kfull(
    const float* __restrict__ kvup, const float* __restrict__ kpe, int kpeStride,
    float* __restrict__ kfull)
{
    size_t idx = (size_t)blockIdx.x * 256 + threadIdx.x;
    const size_t total = (size_t)TT * NH * (DQ + DR);
    if (idx >= total) return;
    int d = (int)(idx % (DQ + DR));
    size_t th = idx / (DQ + DR);
    int h = (int)(th % NH);
    int t = (int)(th / NH);
    float v;
    if (d < DQ) v = kvup[(size_t)t * (NH * (DQ + DV)) + h * (DQ + DV) + d];
    else        v = kpe[(size_t)t * kpeStride + (d - DQ)];
    kfull[idx] = v;
}

// ---------------- causal softmax (in place; exact zeros above diagonal) -----------
__global__ void __launch_bounds__(256) softmax_kernel(float* __restrict__ scores)
{
    const int q = blockIdx.x;
    const int h = blockIdx.y;   // group-local head index
    float* row = scores + ((size_t)h * TT + (size_t)q) * TT;
    const int n = q + 1;
    const float scale = 0.07216878364870323f;  // (DQ+DR)^-0.5

    float m = -3.4e38f;
    for (int k = threadIdx.x; k < n; k += 256) m = fmaxf(m, row[k]);
    m = blockReduceMax(m);

    float s = 0.0f;
    for (int k = threadIdx.x; k < n; k += 256) {
        float e = __expf((row[k] - m) * scale);
        row[k] = e;
        s += e;
    }
    s = blockReduceSum(s);
    float inv = 1.0f / s;
    for (int k = threadIdx.x; k < n; k += 256) row[k] *= inv;
    for (int k = n + threadIdx.x; k < TT; k += 256) row[k] = 0.0f;
}

// ---------------- launcher ----------------
extern "C" void kernel_launch(void* const* d_in, const int* in_sizes, int n_in,
                              void* d_out, int out_size)
{
    const int*   positions = (const int*)  d_in[0];
    const float* hidden    = (const float*)d_in[1];
    const float* w_qa      = (const float*)d_in[2];
    const float* gamma_q   = (const float*)d_in[3];
    const float* w_qb      = (const float*)d_in[4];
    const float* w_kva     = (const float*)d_in[5];
    const float* gamma_kv  = (const float*)d_in[6];
    const float* w_kvb     = (const float*)d_in[7];
    const float* w_o       = (const float*)d_in[8];
    float* out = (float*)d_out;

    float *wcat, *qakv, *q, *kvup, *kfull, *scores, *attnout;
    cudaGetSymbolAddress((void**)&wcat,    g_wcat);
    cudaGetSymbolAddress((void**)&qakv,    g_qakv);
    cudaGetSymbolAddress((void**)&q,       g_q);
    cudaGetSymbolAddress((void**)&kvup,    g_kvup);
    cudaGetSymbolAddress((void**)&kfull,   g_kfull);
    cudaGetSymbolAddress((void**)&scores,  g_scores);
    cudaGetSymbolAddress((void**)&attnout, g_attnout);

    // 0) wcat = [w_qa | w_kva]
    {
        size_t total = (size_t)HIDDEN * NCAT;
        concat_w<<<(unsigned)((total + 255) / 256), 256>>>(w_qa, w_kva, wcat);
    }

    // 1) qakv = hidden @ wcat          (2048x2112, K=5120)
    mma_nn<false><<<dim3((NCAT + 127) / 128, TT / 128, 1), 256>>>(
        TT, NCAT, HIDDEN, hidden, HIDDEN, 0, wcat, NCAT, 0, qakv, NCAT, 0);

    // 2) rmsnorm on q_a part (cols 0..1535) and kv_c part (cols 1536..2047)
    rmsnorm_kernel<<<TT, 256>>>(qakv, gamma_q, QLORA, NCAT);
    rmsnorm_kernel<<<TT, 256>>>(qakv + QLORA, gamma_kv, KVLORA, NCAT);

    // 3) q = q_c @ w_qb                (2048x6144, K=1536)
    mma_nn<false><<<dim3(NH * (DQ + DR) / 128, TT / 128, 1), 256>>>(
        TT, NH * (DQ + DR), QLORA, qakv, NCAT, 0, w_qb, NH * (DQ + DR), 0,
        q, NH * (DQ + DR), 0);

    // 4) kv_up = kv_c @ w_kvb          (2048x8192, K=512)
    mma_nn<false><<<dim3(NH * (DQ + DV) / 128, TT / 128, 1), 256>>>(
        TT, NH * (DQ + DV), KVLORA, qakv + QLORA, NCAT, 0, w_kvb, NH * (DQ + DV), 0,
        kvup, NH * (DQ + DV), 0);

    // 5) RoPE on q_pe (per head) and k_pe (cols 2048..2111 of qakv)
    rope_kernel<<<TT, 256>>>(q, qakv + QLORA + KVLORA, NCAT, positions);

    // 6) K_full assembly
    {
        size_t total = (size_t)TT * NH * (DQ + DR);
        assemble_kfull<<<(unsigned)((total + 255) / 256), 256>>>(
            kvup, qakv + QLORA + KVLORA, NCAT, kfull);
    }

    // 7-9) attention, 4 groups of 8 heads (128 MB score scratch reused)
    for (int grp = 0; grp < NH / NHG; grp++) {
        const int hOff = grp * NHG;

        mma_nt<true><<<dim3(TT / 128, TT / 128, NHG), 256>>>(
            TT, TT, DQ + DR,
            q     + (size_t)hOff * (DQ + DR), NH * (DQ + DR), (long long)(DQ + DR),
            kfull + (size_t)hOff * (DQ + DR), NH * (DQ + DR), (long long)(DQ + DR),
            scores, TT, (long long)TT * TT);

        softmax_kernel<<<dim3(TT, NHG), 256>>>(scores);

        mma_nn<true><<<dim3(DV / 128, TT / 128, NHG), 256>>>(
            TT, DV, TT,
            scores, TT, (long long)TT * TT,
            kvup + DQ + (size_t)hOff * (DQ + DV), NH * (DQ + DV), (long long)(DQ + DV),
            attnout + (size_t)hOff * DV, NH * DV, (long long)DV);
    }

    // 10) out = attn_out @ w_o         (2048x5120, K=4096)
    mma_nn<false><<<dim3(HIDDEN / 128, TT / 128, 1), 256>>>(
        TT, HIDDEN, NH * DV, attnout, NH * DV, 0, w_o, HIDDEN, 0, out, HIDDEN, 0);
}